// round 15
// baseline (speedup 1.0000x reference)
#include <cuda_runtime.h>
#include <stdint.h>
#include <math.h>

// Problem constants
#define CB   4          // batch
#define CTT  4160       // total tokens = W + F
#define CF   4096       // frames
#define CWN  64         // windows (word tokens)
#define CE   256        // embed dim
#define CH   4          // heads
#define CD   64         // head dim
#define LS   15         // local window
#define HALO 7
#define QSCALE 0.125f   // 64^-0.5 (exact power of two)

// Scratch (device globals: allocation-free)
__device__ float g_qkv [CB * CTT * 768];   // (b,t, [Q|K|V] x 256)
__device__ float g_expa[CB * CF  * CE];    // (b,f,e)
__device__ float g_attn[CB * CTT * CE];    // (b,t,e) pre-output-projection

__device__ __forceinline__ unsigned int f2tf(float x) {
    unsigned int r;
    asm("cvt.rna.tf32.f32 %0, %1;" : "=r"(r) : "f"(x));
    return r;
}

__device__ __forceinline__ void mma_tf32(float* d, const unsigned int* a,
                                         const unsigned int* b) {
    asm volatile(
        "mma.sync.aligned.m16n8k8.row.col.f32.tf32.tf32.f32 "
        "{%0,%1,%2,%3}, {%4,%5,%6,%7}, {%8,%9}, {%0,%1,%2,%3};"
        : "+f"(d[0]), "+f"(d[1]), "+f"(d[2]), "+f"(d[3])
        : "r"(a[0]), "r"(a[1]), "r"(a[2]), "r"(a[3]), "r"(b[0]), "r"(b[1]));
}

__device__ __forceinline__ void cp16(void* smem, const void* gmem) {
    unsigned int saddr = (unsigned int)__cvta_generic_to_shared(smem);
    asm volatile("cp.async.cg.shared.global [%0], [%1], 16;"
                 :: "r"(saddr), "l"(gmem));
}
// cp.async with src-size: bytes beyond src_sz are zero-filled (src_sz=0 -> all zeros)
__device__ __forceinline__ void cp16z(void* smem, const void* gmem, int src_sz) {
    unsigned int saddr = (unsigned int)__cvta_generic_to_shared(smem);
    asm volatile("cp.async.cg.shared.global [%0], [%1], 16, %2;"
                 :: "r"(saddr), "l"(gmem), "r"(src_sz));
}
#define CP_COMMIT() asm volatile("cp.async.commit_group;" ::: "memory")
#define CP_WAIT(n)  asm volatile("cp.async.wait_group %0;" :: "n"(n) : "memory")

// ---------------------------------------------------------------------------
// TF32 tensor-core GEMM, 2-stage double-buffered cp.async pipeline.
// C[M x N] = A[M x K] @ B[K x N] + bias.  BM x 128 tile, BK=32, 256 thr,
// 8 warps as 2(m) x 4(n); warp tile (BM/2) x 32.
// ---------------------------------------------------------------------------
#define GEMM_SMEM_BYTES(BM) ((2 * ((BM) * 36) + 2 * (32 * 136)) * 4)

template <int BM, int N, int K>
__device__ __forceinline__ void tf32_gemm_core(const float* __restrict__ A,
                                               const float* __restrict__ B,
                                               const float* __restrict__ bias,
                                               float* __restrict__ C)
{
    constexpr int BK = 32;
    constexpr int ITERS = K / BK;
    constexpr int MI = BM / 32;            // m-subtiles per warp (16-row units x2)
    constexpr int AS_ST = BM * 36;
    constexpr int BS_ST = 32 * 136;

    extern __shared__ float gsm[];
    float* Asm = gsm;                 // [2][BM][36]
    float* Bsm = gsm + 2 * AS_ST;     // [2][32][136]

    const int tid  = threadIdx.x;
    const int warp = tid >> 5, lane = tid & 31;
    const int wm_  = warp >> 2;            // 0..1 -> m offset * (BM/2)
    const int wn_  = warp & 3;             // 0..3 -> n offset * 32
    const int gid  = lane >> 2;
    const int tg   = lane & 3;
    const int m0   = blockIdx.y * BM;
    const int n0   = blockIdx.x * 128;

    auto issue_stage = [&](int s, int k0) {
        float* as = Asm + s * AS_ST;
        float* bs = Bsm + s * BS_ST;
        #pragma unroll
        for (int p = 0; p < BM / 32; p++) {
            int id  = tid + p * 256;
            int row = id >> 3;
            int kc  = (id & 7) * 4;
            cp16(&as[row * 36 + kc], A + (size_t)(m0 + row) * K + k0 + kc);
        }
        #pragma unroll
        for (int p = 0; p < 4; p++) {
            int id   = tid + p * 256;
            int krow = id >> 5;
            int nc   = (id & 31) * 4;
            cp16(&bs[krow * 136 + nc], B + (size_t)(k0 + krow) * N + n0 + nc);
        }
        CP_COMMIT();
    };

    float acc[MI][4][4] = {};

    issue_stage(0, 0);

    for (int it = 0; it < ITERS; it++) {
        if (it + 1 < ITERS) {
            issue_stage((it + 1) & 1, (it + 1) * BK);
            CP_WAIT(1);           // stage `it` complete; `it+1` still in flight
        } else {
            CP_WAIT(0);
        }
        __syncthreads();

        const int s = it & 1;
        const float* as = Asm + s * AS_ST;
        const float* bs = Bsm + s * BS_ST;

        #pragma unroll
        for (int ks = 0; ks < 4; ks++) {
            const int kb = ks * 8;
            unsigned int af[MI][4], bf[4][2];
            #pragma unroll
            for (int mi = 0; mi < MI; mi++) {
                int mr = wm_ * (BM / 2) + mi * 16 + gid;
                af[mi][0] = f2tf(as[ mr      * 36 + kb + tg    ]);
                af[mi][1] = f2tf(as[(mr + 8) * 36 + kb + tg    ]);
                af[mi][2] = f2tf(as[ mr      * 36 + kb + tg + 4]);
                af[mi][3] = f2tf(as[(mr + 8) * 36 + kb + tg + 4]);
            }
            #pragma unroll
            for (int ni = 0; ni < 4; ni++) {
                int nc = wn_ * 32 + ni * 8 + gid;
                bf[ni][0] = f2tf(bs[(kb + tg    ) * 136 + nc]);
                bf[ni][1] = f2tf(bs[(kb + tg + 4) * 136 + nc]);
            }
            #pragma unroll
            for (int mi = 0; mi < MI; mi++)
                #pragma unroll
                for (int ni = 0; ni < 4; ni++)
                    mma_tf32(acc[mi][ni], af[mi], bf[ni]);
        }
        __syncthreads();   // protect stage buffers before next iteration's issue
    }

    #pragma unroll
    for (int ni = 0; ni < 4; ni++) {
        int c0 = n0 + wn_ * 32 + ni * 8 + tg * 2;
        float b0v = bias[c0], b1v = bias[c0 + 1];
        #pragma unroll
        for (int mi = 0; mi < MI; mi++) {
            int r0 = m0 + wm_ * (BM / 2) + mi * 16 + gid;
            float2 o0 = { acc[mi][ni][0] + b0v, acc[mi][ni][1] + b1v };
            float2 o1 = { acc[mi][ni][2] + b0v, acc[mi][ni][3] + b1v };
            *(float2*)(C + (size_t)r0 * N + c0)       = o0;
            *(float2*)(C + (size_t)(r0 + 8) * N + c0) = o1;
        }
    }
}

__global__ __launch_bounds__(256, 2)
void k_qkv(const float* __restrict__ x, const float* __restrict__ Wq,
           const float* __restrict__ bq)
{
    tf32_gemm_core<128, 768, 256>(x, Wq, bq, g_qkv);
}

// BM=64 -> 520 blocks, 53.2 KB smem, 3 blocks/SM: latency-hiding for small grid
__global__ __launch_bounds__(256, 3)
void k_out(const float* __restrict__ Wo, const float* __restrict__ bo,
           float* __restrict__ out)
{
    tf32_gemm_core<64, 256, 256>(g_attn, Wo, bo, out);
}

// ---------------------------------------------------------------------------
// expa[b,f,e] = sum_w wm[b,w,f] * x[b,w,e]   (K = 64 windows, fp32 exact)
// gridDim.z == 5: the z==4 slice does the word-token passthrough copy.
// ---------------------------------------------------------------------------
__global__ __launch_bounds__(256)
void k_expa(const float* __restrict__ wm, const float* __restrict__ x)
{
    if (blockIdx.z == 4) {
        // word-token rows pass through: g_attn[b, t<64, :] = x[b, t<64, :]
        int i = ((blockIdx.y * 4 + blockIdx.x) * 256) + threadIdx.x; // 0..65535
        int b = i >> 14;
        int r = i & 16383;
        g_attn[(size_t)b * CTT * CE + r] = x[(size_t)b * CTT * CE + r];
        return;
    }

    __shared__ float As[64][64];  // [w][f]
    __shared__ float Bs[64][64];  // [w][e]

    const int b  = blockIdx.z;
    const int f0 = blockIdx.y * 64;
    const int e0 = blockIdx.x * 64;
    const int tid = threadIdx.x;

    for (int i = tid; i < 64 * 16; i += 256) {
        int w  = i >> 4;
        int c4 = (i & 15) * 4;
        *(float4*)&As[w][c4] =
            *(const float4*)(wm + (size_t)(b * CWN + w) * CF + f0 + c4);
        *(float4*)&Bs[w][c4] =
            *(const float4*)(x + (size_t)(b * CTT + w) * CE + e0 + c4);
    }
    __syncthreads();

    const int tx = tid & 15, ty = tid >> 4;
    float acc[4][4] = {};
    #pragma unroll 8
    for (int w = 0; w < 64; w++) {
        float ra[4], rb[4];
        *(float4*)ra = *(const float4*)&As[w][ty * 4];
        *(float4*)rb = *(const float4*)&Bs[w][tx * 4];
        #pragma unroll
        for (int i = 0; i < 4; i++)
            #pragma unroll
            for (int j = 0; j < 4; j++)
                acc[i][j] = fmaf(ra[i], rb[j], acc[i][j]);
    }

    #pragma unroll
    for (int i = 0; i < 4; i++) {
        float4 o = { acc[i][0], acc[i][1], acc[i][2], acc[i][3] };
        *(float4*)(g_expa + (size_t)(b * CF + f0 + ty * 4 + i) * CE + e0 + tx * 4) = o;
    }
}

// ---------------------------------------------------------------------------
// Attention v4 (unchanged): shuffle-free scores, Q via gmem broadcast,
// 46.2 KB smem, 4 blocks/SM.
// ---------------------------------------------------------------------------
#define KST 68
#define AROWS 78
#define AOFF_K 0
#define AOFF_V (AROWS * KST)                 // 5304
#define AOFF_S (2 * AROWS * KST)             // 10608
#define AOFF_S0 (AOFF_S + 64 * 17)           // 11696
#define AOFF_W0 (AOFF_S0 + 64)               // 11760
#define ATTN_WORDS (AOFF_W0 + 64)            // 11824 -> 47296 B

__global__ __launch_bounds__(256, 4)
void k_attn()
{
    extern __shared__ float sa[];
    float* sK = sa + AOFF_K;
    float* sV = sa + AOFF_V;
    float* sS = sa + AOFF_S;
    float* s0 = sa + AOFF_S0;
    float* w0 = sa + AOFF_W0;

    const int n = blockIdx.y, c = blockIdx.x;
    const int b = n >> 2, h = n & 3;
    const int tid = threadIdx.x;
    const int warp = tid >> 5, lane = tid & 31;

    const float* Qg = g_qkv + (size_t)(b * CTT + CWN + c * 64) * 768 + h * 64;

    // ---- stage K/V halo (zero-filled OOB) via cp.async ----
    for (int i = tid; i < AROWS * 16; i += 256) {
        int row = i >> 4, c4 = (i & 15) * 4;
        int gf  = c * 64 - HALO + row;
        int ok  = (gf >= 0 && gf < CF);
        int gfc = ok ? gf : 0;
        const float* base = g_qkv + (size_t)(b * CTT + CWN + gfc) * 768 + h * 64 + c4;
        cp16z(&sK[row * KST + c4], base + 256, ok ? 16 : 0);
        cp16z(&sV[row * KST + c4], base + 512, ok ? 16 : 0);
    }
    CP_COMMIT();

    // ---- word-token scores from gmem Q (overlaps with K/V arrival) ----
    #pragma unroll
    for (int fi = 0; fi < 8; fi++) {
        int lf = warp * 8 + fi;
        const float* qp = Qg + (size_t)lf * 768;
        const float* ep = g_expa + (size_t)(b * CF + c * 64 + lf) * CE + h * 64;
        float p = qp[lane] * ep[lane] + qp[lane + 32] * ep[lane + 32];
        #pragma unroll
        for (int off = 16; off; off >>= 1)
            p += __shfl_xor_sync(0xffffffffu, p, off);
        if (lane == 0) s0[lf] = p * QSCALE;
    }

    CP_WAIT(0);
    __syncthreads();

    // ---- local scores: lane-per-score, Q broadcast from gmem, K from smem ----
    {
        const int j    = lane & 15;
        const int half = lane >> 4;
        #pragma unroll
        for (int pass = 0; pass < 4; pass++) {
            int f = pass * 16 + warp * 2 + half;
            if (j < LS) {
                const float* qr = Qg + (size_t)f * 768;
                const float* kr = sK + (f + j) * KST;
                float a0 = 0.f, a1 = 0.f;
                #pragma unroll
                for (int e = 0; e < 64; e += 4) {
                    float4 qv = *(const float4*)(qr + e);
                    float4 kv = *(const float4*)(kr + e);
                    a0 = fmaf(qv.x, kv.x, a0);
                    a1 = fmaf(qv.y, kv.y, a1);
                    a0 = fmaf(qv.z, kv.z, a0);
                    a1 = fmaf(qv.w, kv.w, a1);
                }
                sS[f * 17 + j] = (a0 + a1) * QSCALE;
            }
        }
    }
    __syncthreads();

    // ---- chunk softmax (warp 0) + local softmax (tid<64) ----
    if (warp == 0) {
        float v0 = s0[lane], v1 = s0[lane + 32];
        float M = fmaxf(v0, v1);
        #pragma unroll
        for (int off = 16; off; off >>= 1)
            M = fmaxf(M, __shfl_xor_sync(0xffffffffu, M, off));
        float S = expf(v0 - M) + expf(v1 - M);
        #pragma unroll
        for (int off = 16; off; off >>= 1)
            S += __shfl_xor_sync(0xffffffffu, S, off);
        float Sinv = 1.f / S;
        w0[lane]      = expf(v0 - M) * Sinv;
        w0[lane + 32] = expf(v1 - M) * Sinv;
    }
    if (tid < 64) {
        float p[LS];
        #pragma unroll
        for (int j = 0; j < LS; j++) p[j] = sS[tid * 17 + j];
        float mx = p[0];
        #pragma unroll
        for (int j = 1; j < LS; j++) mx = fmaxf(mx, p[j]);
        float s = 0.f;
        #pragma unroll
        for (int j = 0; j < LS; j++) { p[j] = expf(p[j] - mx); s += p[j]; }
        float inv = 1.f / s;
        #pragma unroll
        for (int j = 0; j < LS; j++) sS[tid * 17 + j] = p[j] * inv;
    }
    __syncthreads();

    // ---- output: o = w0*expa + sum_j w_j * V ----
    #pragma unroll
    for (int fi = 0; fi < 8; fi++) {
        int lf = warp * 8 + fi;
        const float* ep = g_expa + (size_t)(b * CF + c * 64 + lf) * CE + h * 64;
        float wv = w0[lf];
        float o0 = wv * ep[lane];
        float o1 = wv * ep[lane + 32];
        #pragma unroll
        for (int j = 0; j < LS; j++) {
            float wj = sS[lf * 17 + j];
            const float* vr = sV + (lf + j) * KST;
            o0 = fmaf(wj, vr[lane],      o0);
            o1 = fmaf(wj, vr[lane + 32], o1);
        }
        float* op = g_attn + (size_t)(b * CTT + CWN + c * 64 + lf) * CE + h * 64;
        op[lane]      = o0;
        op[lane + 32] = o1;
    }
}

// ---------------------------------------------------------------------------
extern "C" void kernel_launch(void* const* d_in, const int* in_sizes, int n_in,
                              void* d_out, int out_size)
{
    const float *x = nullptr, *wm = nullptr, *Wq = nullptr, *bq = nullptr,
                *Wo = nullptr, *bo = nullptr;
    for (int i = 0; i < n_in; i++) {
        switch (in_sizes[i]) {
            case 4259840: x  = (const float*)d_in[i]; break;  // (4,4160,256)
            case 1048576: wm = (const float*)d_in[i]; break;  // (4,64,4096)
            case  196608: Wq = (const float*)d_in[i]; break;  // (256,768)
            case     768: bq = (const float*)d_in[i]; break;
            case   65536: Wo = (const float*)d_in[i]; break;  // (256,256)
            case     256: bo = (const float*)d_in[i]; break;
            default: break;
        }
    }

    cudaFuncSetAttribute(k_qkv, cudaFuncAttributeMaxDynamicSharedMemorySize,
                         GEMM_SMEM_BYTES(128));
    cudaFuncSetAttribute(k_out, cudaFuncAttributeMaxDynamicSharedMemorySize,
                         GEMM_SMEM_BYTES(64));
    cudaFuncSetAttribute(k_attn, cudaFuncAttributeMaxDynamicSharedMemorySize,
                         ATTN_WORDS * 4);

    // 1) qkv = x @ W_qkv + b_qkv   (tf32, BM=128, 2-stage double buffer)
    k_qkv<<<dim3(768 / 128, (CB * CTT) / 128), 256, GEMM_SMEM_BYTES(128)>>>(x, Wq, bq);
    // 2) expa = wm^T @ x_words  (+ z==4 slice: word-token passthrough)
    k_expa<<<dim3(CE / 64, CF / 64, CB + 1), 256>>>(wm, x);
    // 3) shuffle-free SIMT attention, 4 blocks/SM
    k_attn<<<dim3(CF / 64, CB * CH), 256, ATTN_WORDS * 4>>>();
    // 4) out = attn @ W_out + b_out (tf32, BM=64 for occupancy, 520 blocks)
    k_out<<<dim3(256 / 128, (CB * CTT) / 64), 256, GEMM_SMEM_BYTES(64)>>>(Wo, bo, (float*)d_out);
}